// round 10
// baseline (speedup 1.0000x reference)
#include <cuda_runtime.h>

#define BB 16
#define HH 512
#define WW 512
#define HW (HH*WW)
#define NN (BB*HW)
#define WPR 16                 // words per row
#define WPI (HH*WPR)           // words per image = 8192
#define TOT (BB*WPI)           // total words = 131072

#define CAP 24576              // max runs handled in SMEM per image
#define PTPB 256

__device__ unsigned g_F[TOT];
__device__ unsigned g_G[TOT];
__device__ unsigned g_H[TOT];
// global fallback union-find scratch (per-image slices), used only if runs > CAP
__device__ int g_FL[NN];
__device__ int g_FS[NN];

// ---------------- bit helpers ----------------
__device__ __forceinline__ int runlen(unsigned m, int j) {
    unsigned nt = ~(m >> j);
    return nt ? (__ffs(nt) - 1) : (32 - j);
}
__device__ __forceinline__ unsigned runmask(int j, int e) {
    return (e >= 32) ? 0xffffffffu : (((1u << e) - 1u) << j);
}

template<bool INV>
__device__ __forceinline__ unsigned ldmask(const unsigned* Fimg, int q) {
    unsigned m = Fimg[q];
    return INV ? ~m : m;
}
// run-start bits of word q (runs span words within a row; rows never span)
template<bool INV>
__device__ __forceinline__ unsigned smask(const unsigned* Fimg, int q) {
    unsigned m = ldmask<INV>(Fimg, q);
    unsigned carry = (q & 15) ? (ldmask<INV>(Fimg, q - 1) >> 31) : 0u;
    return m & ~((m << 1) | carry);
}
// compact run id of the run containing set bit j of word q
__device__ __forceinline__ int rid_of(const int* base, unsigned st, int q, int j) {
    unsigned low = (j >= 31) ? 0xffffffffu : ((2u << j) - 1u);
    return base[q] + __popc(st & low) - 1;
}

// ---------------- union-find on compact run ids ----------------
__device__ __forceinline__ int uf_find(int* P, int i) {
    volatile int* V = P;
    int p;
    while ((p = V[i]) != i) {
        int gp = V[p];
        if (gp == p) return p;
        atomicCAS(&P[i], p, gp);      // CAS halving: safe vs concurrent atomicMin
        i = gp;
    }
    return i;
}
__device__ void uf_unite(int* P, int a, int b) {
    while (true) {
        a = uf_find(P, a);
        b = uf_find(P, b);
        if (a == b) return;
        if (a > b) { int t = a; a = b; b = t; }
        int old = atomicMin(&P[b], a);
        if (old == b) return;
        b = old;
    }
}

// ---------------- pack ----------------
__global__ void k_pack(const float* __restrict__ in) {
    int i = blockIdx.x * blockDim.x + threadIdx.x;
    unsigned b = __ballot_sync(0xffffffffu, in[i] > 0.0f);
    if ((i & 31) == 0) g_F[i >> 5] = b;
}

// ---------------- per-image pipeline block ----------------
__shared__ int s_warp[32];
__shared__ int s_R;
__shared__ int s_nc;

// One CCL pass on Fimg. FILL: add small bg components; else remove small fg.
template<bool INV, bool GUARD, bool FILL>
__device__ void ccl_pass(unsigned* Fimg, int b, int thr,
                         int* s_base, int* s_par, int* s_siz) {
    int tid = threadIdx.x, lane = tid & 31, wid = tid >> 5;

    // --- 1. run-start counts + block prefix sum -> s_base, s_R ---
    int cs[8], c = 0;
#pragma unroll
    for (int k = 0; k < 8; k++) {
        cs[k] = __popc(smask<INV>(Fimg, tid * 8 + k));
        c += cs[k];
    }
    int x = c;
#pragma unroll
    for (int d = 1; d < 32; d <<= 1) {
        int y = __shfl_up_sync(0xffffffffu, x, d);
        if (lane >= d) x += y;
    }
    if (lane == 31) s_warp[wid] = x;
    __syncthreads();
    if (wid == 0) {
        int v = s_warp[lane];
#pragma unroll
        for (int d = 1; d < 32; d <<= 1) {
            int y = __shfl_up_sync(0xffffffffu, v, d);
            if (lane >= d) v += y;
        }
        s_warp[lane] = v;
    }
    __syncthreads();
    int excl = x - c + (wid ? s_warp[wid - 1] : 0);
    if (tid == 1023) s_R = excl + c;
    int run = excl;
#pragma unroll
    for (int k = 0; k < 8; k++) { s_base[tid * 8 + k] = run; run += cs[k]; }
    if (tid == 0) s_nc = 0;
    __syncthreads();

    const int R = s_R;
    int* par = (R <= CAP) ? s_par : (g_FL + b * HW);
    int* siz = (R <= CAP) ? s_siz : (g_FS + b * HW);

    // --- 2. init ---
    for (int r = tid; r < R; r += 1024) { par[r] = r; siz[r] = 0; }
    __syncthreads();

    // --- 3. vertical unions (horizontal implicit: runs span words) ---
    for (int k = 0; k < 8; k++) {
        int q = tid + k * 1024;
        int y = q >> 4;
        if (y == 0) continue;
        unsigned cur = ldmask<INV>(Fimg, q);
        if (!cur) continue;
        unsigned up = ldmask<INV>(Fimg, q - WPR);
        unsigned ov = cur & up;
        if (!ov) continue;
        unsigned st_c = smask<INV>(Fimg, q);
        unsigned st_u = smask<INV>(Fimg, q - WPR);
        unsigned starts = ov & ~(ov << 1);   // redundant cross-word repeats are harmless
        while (starts) {
            int j = __ffs(starts) - 1;
            starts &= starts - 1;
            uf_unite(par, rid_of(s_base, st_c, q, j), rid_of(s_base, st_u, q - WPR, j));
        }
    }
    __syncthreads();

    // --- 4. compress + component count ---
    for (int r = tid; r < R; r += 1024) {
        int root = uf_find(par, r);
        par[r] = root;                       // plain store: monotone toward root
        if (GUARD && root == r) atomicAdd(&s_nc, 1);
    }
    __syncthreads();

    // --- 5. per-word segment size accumulation onto roots ---
    for (int k = 0; k < 8; k++) {
        int q = tid + k * 1024;
        unsigned m = ldmask<INV>(Fimg, q);
        if (!m) continue;
        unsigned st = smask<INV>(Fimg, q);
        while (m) {
            int j = __ffs(m) - 1;
            int e = runlen(m, j);
            atomicAdd(&siz[par[rid_of(s_base, st, q, j)]], e);
            m &= ~runmask(j, e);
        }
    }
    __syncthreads();

    // --- 6. filter / fill ---
    bool act = !GUARD || (s_nc > 1);
    for (int k = 0; k < 8; k++) {
        int q = tid + k * 1024;
        unsigned m = ldmask<INV>(Fimg, q);
        if (!m || !act) continue;
        unsigned st = smask<INV>(Fimg, q);
        unsigned delta = 0, mm = m;
        while (mm) {
            int j = __ffs(mm) - 1;
            int e = runlen(mm, j);
            if (siz[par[rid_of(s_base, st, q, j)]] < thr) delta |= runmask(j, e);
            mm &= ~runmask(j, e);
        }
        if (delta) {
            if (FILL) Fimg[q] |= delta;      // add small bg components
            else      Fimg[q] &= ~delta;     // remove small fg components
        }
    }
    __syncthreads();
}

// ---------------- morphology (per-image, global mem) ----------------
__host__ __device__ constexpr int hwidth(int R, int dy) {
    int w = 0;
    while ((w + 1) * (w + 1) + dy * dy <= R * R) ++w;
    return w;
}

template<int R, bool ER>
__device__ void morph(const unsigned* __restrict__ img, unsigned* __restrict__ out) {
    const unsigned border = ER ? 0xffffffffu : 0u;
    for (int k = 0; k < 8; k++) {
        int q = threadIdx.x + k * 1024;
        int w = q & 15, y = q >> 4;
        unsigned acc = border;
#pragma unroll
        for (int dy = -R; dy <= R; dy++) {
            int yy = y + dy;
            unsigned c, l, r;
            if (yy < 0 || yy >= HH) { c = border; l = border; r = border; }
            else {
                c = img[yy * WPR + w];
                l = (w > 0)  ? img[yy * WPR + w - 1] : border;
                r = (w < 15) ? img[yy * WPR + w + 1] : border;
            }
            unsigned rowacc = c;
            const int wd = hwidth(R, dy);
#pragma unroll
            for (int s = 1; s <= wd; s++) {
                unsigned rs = __funnelshift_r(c, r, s);
                unsigned ls = __funnelshift_l(l, c, s);
                if (ER) rowacc &= rs & ls; else rowacc |= rs | ls;
            }
            if (ER) acc &= rowacc; else acc |= rowacc;
        }
        out[q] = acc;
    }
    __syncthreads();
}

// ---------------- the per-image pipeline kernel (16 blocks) ----------------
__global__ void __launch_bounds__(1024, 1) k_pipe() {
    extern __shared__ int dsm[];
    int* s_base = dsm;                 // WPI
    int* s_par  = dsm + WPI;           // CAP
    int* s_siz  = dsm + WPI + CAP;     // CAP

    int b = blockIdx.x;
    unsigned* F = g_F + b * WPI;
    unsigned* G = g_G + b * WPI;
    unsigned* H = g_H + b * WPI;

    // remove_small_objects(fg, 2000, guarded)
    ccl_pass<false, true , false>(F, b, 2000, s_base, s_par, s_siz);
    // fill small holes (bg comps < 301)
    ccl_pass<true , false, true >(F, b, 301,  s_base, s_par, s_siz);
    // erode disk(2); opening disk(5) = erode + dilate
    morph<2, true >(F, G);
    morph<5, true >(G, H);
    morph<5, false>(H, G);
    // remove_small_objects(fg, 2000, guarded)
    ccl_pass<false, true , false>(G, b, 2000, s_base, s_par, s_siz);
}

// ---------------- final dilate(disk1) + unpack float ----------------
__global__ void k_out(float* __restrict__ out) {
    int g = blockIdx.x * blockDim.x + threadIdx.x;
    int lane = g & 31;
    int t = g >> 5;
    int w = t & 15, y = (t >> 4) & 511, b = t >> 13;
    const unsigned* img = g_G + b * WPI;
    unsigned c = img[y * WPR + w];
    unsigned l = (w > 0)   ? img[y * WPR + w - 1] : 0u;
    unsigned r = (w < 15)  ? img[y * WPR + w + 1] : 0u;
    unsigned u = (y > 0)   ? img[(y - 1) * WPR + w] : 0u;
    unsigned d = (y < 511) ? img[(y + 1) * WPR + w] : 0u;
    unsigned res = c | u | d | __funnelshift_r(c, r, 1) | __funnelshift_l(l, c, 1);
    out[b * HW + y * WW + w * 32 + lane] = (float)((res >> lane) & 1u);
}

// ---------------- launch ----------------
extern "C" void kernel_launch(void* const* d_in, const int* in_sizes, int n_in,
                              void* d_out, int out_size) {
    (void)in_sizes; (void)n_in; (void)out_size;
    const int SMEM = (WPI + 2 * CAP) * (int)sizeof(int);   // 229376 B
    cudaFuncSetAttribute(k_pipe, cudaFuncAttributeMaxDynamicSharedMemorySize, SMEM);

    k_pack<<<NN / PTPB, PTPB>>>((const float*)d_in[0]);
    k_pipe<<<BB, 1024, SMEM>>>();
    k_out<<<NN / PTPB, PTPB>>>((float*)d_out);
}